// round 5
// baseline (speedup 1.0000x reference)
#include <cuda_runtime.h>
#include <math.h>

#define NN 100000
#define EE 1600000
#define SCAN_B 256
#define NBLK ((NN + SCAN_B - 1) / SCAN_B)   // 391

// ---- scratch (__device__ globals; no allocations allowed) ----
__device__ __align__(16) float g_Y[NN * 32];   // [Y0(16)|Y1(16)] per node
__device__ __align__(16) float g_R1[NN * 16];  // x@root1 + b1
__device__ __align__(16) float g_h[NN * 16];   // elu(conv1) output
__device__ __align__(16) float g_Z[NN * 20];   // [Z0(10)|Z1(10)] per node
__device__ __align__(16) float g_R2[NN * 10];  // h@root2 + b2
__device__ int  g_cnt[NN];                     // per-dst edge count
__device__ int  g_cur[NN];                     // scatter cursors
__device__ int  g_rowp[NN];                    // block-local exclusive scan
__device__ int  g_row[NN + 1];                 // final CSR row starts
__device__ int  g_bs[512];                     // block sums (exclusive after scan2)
__device__ __align__(8) int2 g_edge[EE];       // {src, bit_cast(v)} grouped by dst

// ---------------------------------------------------------------------------
// prep: node1 GEMMs (Y0,Y1,R1) + zero CSR counters
// ---------------------------------------------------------------------------
__global__ void prep_kernel(const float* __restrict__ x,
                            const float* __restrict__ W1,
                            const float* __restrict__ root1,
                            const float* __restrict__ b1)
{
    __shared__ float sW[1024];   // W1[k][i][o]
    __shared__ float sR[512];    // root1[i][o]
    __shared__ float sB[16];
    for (int t = threadIdx.x; t < 1024; t += blockDim.x) sW[t] = W1[t];
    for (int t = threadIdx.x; t < 512;  t += blockDim.x) sR[t] = root1[t];
    if (threadIdx.x < 16) sB[threadIdx.x] = b1[threadIdx.x];
    __syncthreads();

    int n = blockIdx.x * blockDim.x + threadIdx.x;
    if (n >= NN) return;

    g_cnt[n] = 0;
    g_cur[n] = 0;

    float xv[32];
    const float4* xp = (const float4*)(x + (size_t)n * 32);
    #pragma unroll
    for (int i = 0; i < 8; i++) {
        float4 t = xp[i];
        xv[4*i+0] = t.x; xv[4*i+1] = t.y; xv[4*i+2] = t.z; xv[4*i+3] = t.w;
    }

    float* Yp = g_Y  + (size_t)n * 32;
    float* Rp = g_R1 + (size_t)n * 16;
    for (int o = 0; o < 16; o++) {
        float y0 = 0.f, y1 = 0.f, r = sB[o];
        #pragma unroll
        for (int i = 0; i < 32; i++) {
            y0 = fmaf(xv[i], sW[i * 16 + o], y0);
            y1 = fmaf(xv[i], sW[512 + i * 16 + o], y1);
            r  = fmaf(xv[i], sR[i * 16 + o], r);
        }
        Yp[o] = y0; Yp[16 + o] = y1; Rp[o] = r;
    }
}

// ---------------------------------------------------------------------------
// CSR build
// ---------------------------------------------------------------------------
__global__ void hist_kernel(const int* __restrict__ ei)
{
    int e = blockIdx.x * blockDim.x + threadIdx.x;
    if (e >= EE) return;
    int d = ei[EE + e];
    if ((unsigned)d < NN) atomicAdd(&g_cnt[d], 1);
}

__global__ void scan1_kernel()
{
    __shared__ int sm[SCAN_B];
    int tid = threadIdx.x;
    int i = blockIdx.x * SCAN_B + tid;
    int v = (i < NN) ? g_cnt[i] : 0;
    sm[tid] = v;
    __syncthreads();
    for (int off = 1; off < SCAN_B; off <<= 1) {
        int t = (tid >= off) ? sm[tid - off] : 0;
        __syncthreads();
        sm[tid] += t;
        __syncthreads();
    }
    if (i < NN) g_rowp[i] = sm[tid] - v;               // exclusive
    if (tid == SCAN_B - 1) g_bs[blockIdx.x] = sm[tid]; // block total
}

__global__ void scan2_kernel()
{
    __shared__ int sm[512];
    int tid = threadIdx.x;
    int v = (tid < NBLK) ? g_bs[tid] : 0;
    sm[tid] = v;
    __syncthreads();
    for (int off = 1; off < 512; off <<= 1) {
        int t = (tid >= off) ? sm[tid - off] : 0;
        __syncthreads();
        sm[tid] += t;
        __syncthreads();
    }
    if (tid < NBLK) g_bs[tid] = sm[tid] - v;           // exclusive
}

__global__ void scan3_kernel()
{
    int i = blockIdx.x * blockDim.x + threadIdx.x;
    if (i < NN) g_row[i] = g_rowp[i] + g_bs[i >> 8];
    if (i == 0) g_row[NN] = EE;
}

__global__ void scatter_kernel(const int* __restrict__ ei,
                               const float* __restrict__ attr)
{
    int e = blockIdx.x * blockDim.x + threadIdx.x;
    if (e >= EE) return;
    int s = ei[e];
    int d = ei[EE + e];
    if ((unsigned)s >= NN || (unsigned)d >= NN) return;
    float v = attr[e];
    int pos = g_row[d] + atomicAdd(&g_cur[d], 1);
    g_edge[pos] = make_int2(s, __float_as_int(v));
}

// ---------------------------------------------------------------------------
// agg1: warp per dst node, half-warp per edge; fused mean + root + ELU -> g_h
// ---------------------------------------------------------------------------
__global__ void agg1_kernel()
{
    int gid = blockIdx.x * blockDim.x + threadIdx.x;
    int w = gid >> 5;
    if (w >= NN) return;
    int lane = threadIdx.x & 31;
    int half = lane >> 4;
    int l = lane & 15;

    int beg = g_row[w], end = g_row[w + 1];
    float acc = 0.f;
    for (int i = beg + half; i < end; i += 2) {
        int2 er = g_edge[i];
        float v  = __int_as_float(er.y);
        float c0 = fmaxf(0.f, 1.f - fabsf(v));
        float c1 = fmaxf(0.f, 1.f - fabsf(v - 1.f));
        const float* yp = g_Y + (size_t)er.x * 32;
        acc = fmaf(c0, yp[l], fmaf(c1, yp[16 + l], acc));
    }
    acc += __shfl_xor_sync(0xffffffffu, acc, 16);

    float deg = (float)(end - beg);
    float t = acc / fmaxf(deg, 1.f) + g_R1[(size_t)w * 16 + l];
    float h = (t > 0.f) ? t : expm1f(t);                // ELU alpha=1
    if (half == 0) g_h[(size_t)w * 16 + l] = h;
}

// ---------------------------------------------------------------------------
// node2: Z0 = h@W2[0], Z1 = h@W2[1], R2 = h@root2 + b2
// ---------------------------------------------------------------------------
__global__ void node2_kernel(const float* __restrict__ W2,
                             const float* __restrict__ root2,
                             const float* __restrict__ b2)
{
    __shared__ float sW[320];
    __shared__ float sR[160];
    __shared__ float sB[10];
    for (int t = threadIdx.x; t < 320; t += blockDim.x) sW[t] = W2[t];
    for (int t = threadIdx.x; t < 160; t += blockDim.x) sR[t] = root2[t];
    if (threadIdx.x < 10) sB[threadIdx.x] = b2[threadIdx.x];
    __syncthreads();

    int n = blockIdx.x * blockDim.x + threadIdx.x;
    if (n >= NN) return;

    float h[16];
    const float4* hp = (const float4*)(g_h + (size_t)n * 16);
    #pragma unroll
    for (int i = 0; i < 4; i++) {
        float4 t = hp[i];
        h[4*i+0] = t.x; h[4*i+1] = t.y; h[4*i+2] = t.z; h[4*i+3] = t.w;
    }

    float* zp = g_Z  + (size_t)n * 20;
    float* r2 = g_R2 + (size_t)n * 10;
    for (int o = 0; o < 10; o++) {
        float z0 = 0.f, z1 = 0.f, r = sB[o];
        #pragma unroll
        for (int i = 0; i < 16; i++) {
            z0 = fmaf(h[i], sW[i * 10 + o], z0);
            z1 = fmaf(h[i], sW[160 + i * 10 + o], z1);
            r  = fmaf(h[i], sR[i * 10 + o], r);
        }
        zp[o] = z0; zp[10 + o] = z1; r2[o] = r;
    }
}

// ---------------------------------------------------------------------------
// agg2: warp per dst node + fused mean + root + log_softmax -> out
// ---------------------------------------------------------------------------
__global__ void agg2_kernel(float* __restrict__ out)
{
    int gid = blockIdx.x * blockDim.x + threadIdx.x;
    int w = gid >> 5;
    if (w >= NN) return;
    int lane = threadIdx.x & 31;
    int half = lane >> 4;
    int l = lane & 15;

    int beg = g_row[w], end = g_row[w + 1];
    float acc = 0.f;
    for (int i = beg + half; i < end; i += 2) {
        int2 er = g_edge[i];
        float v  = __int_as_float(er.y);
        float c0 = fmaxf(0.f, 1.f - fabsf(v));
        float c1 = fmaxf(0.f, 1.f - fabsf(v - 1.f));
        if (l < 10) {
            const float* zp = g_Z + (size_t)er.x * 20;
            acc = fmaf(c0, zp[l], fmaf(c1, zp[10 + l], acc));
        }
    }
    acc += __shfl_xor_sync(0xffffffffu, acc, 16);

    float deg = (float)(end - beg);
    float o = (l < 10) ? (acc / fmaxf(deg, 1.f) + g_R2[(size_t)w * 10 + l])
                       : -INFINITY;

    // log-softmax over 10 classes held in lanes 0..9 of each 16-lane half
    float mx = o;
    #pragma unroll
    for (int off = 8; off >= 1; off >>= 1)
        mx = fmaxf(mx, __shfl_xor_sync(0xffffffffu, mx, off));
    float ex = (l < 10) ? expf(o - mx) : 0.f;
    float sum = ex;
    #pragma unroll
    for (int off = 8; off >= 1; off >>= 1)
        sum += __shfl_xor_sync(0xffffffffu, sum, off);
    float lse = mx + logf(sum);

    if (half == 0 && l < 10) out[(size_t)w * 10 + l] = o - lse;
}

// ---------------------------------------------------------------------------
extern "C" void kernel_launch(void* const* d_in, const int* in_sizes, int n_in,
                              void* d_out, int out_size)
{
    (void)out_size;
    int ix = -1, iei = -1, iattr = -1, iW1 = -1, ir1 = -1, ib1 = -1,
        iW2 = -1, ir2 = -1, ib2 = -1;
    int big[2]; int nbig = 0;
    for (int i = 0; i < n_in; i++) {
        switch (in_sizes[i]) {
            case 3200000: if (nbig < 2) big[nbig++] = i; break;
            case 1600000: iattr = i; break;
            case 1024:    iW1 = i; break;
            case 512:     ir1 = i; break;
            case 16:      ib1 = i; break;
            case 320:     iW2 = i; break;
            case 160:     ir2 = i; break;
            case 10:      ib2 = i; break;
            default: break;
        }
    }
    if (nbig == 2) {
        bool insertion = (big[0] == 0 && big[1] == 1 && iattr == 2);
        if (insertion) { ix = big[0]; iei = big[1]; }
        else           { iei = big[0]; ix = big[1]; }
    }

    const float* x     = (const float*)d_in[ix];
    const int*   ei    = (const int*)d_in[iei];      // int32 edge_index
    const float* attr  = (const float*)d_in[iattr];
    const float* W1    = (const float*)d_in[iW1];
    const float* root1 = (const float*)d_in[ir1];
    const float* b1    = (const float*)d_in[ib1];
    const float* W2    = (const float*)d_in[iW2];
    const float* root2 = (const float*)d_in[ir2];
    const float* b2    = (const float*)d_in[ib2];
    float* out = (float*)d_out;

    prep_kernel<<<(NN + 255) / 256, 256>>>(x, W1, root1, b1);
    hist_kernel<<<(EE + 255) / 256, 256>>>(ei);
    scan1_kernel<<<NBLK, SCAN_B>>>();
    scan2_kernel<<<1, 512>>>();
    scan3_kernel<<<(NN + 255) / 256, 256>>>();
    scatter_kernel<<<(EE + 255) / 256, 256>>>(ei, attr);
    agg1_kernel<<<(NN * 32 + 255) / 256, 256>>>();
    node2_kernel<<<(NN + 255) / 256, 256>>>(W2, root2, b2);
    agg2_kernel<<<(NN * 32 + 255) / 256, 256>>>(out);
}

// round 6
// speedup vs baseline: 1.7880x; 1.7880x over previous
#include <cuda_runtime.h>
#include <math.h>

#define NN 100000
#define EE 1600000

// ---- scratch (__device__ globals; no allocations allowed) ----
__device__ __align__(16) float g_Y[NN * 32];     // [Y0(16) | Y1(16)] per node, 128B row
__device__ __align__(16) float g_R1[NN * 16];    // x@root1 + b1
__device__ __align__(16) float g_acc1[NN * 16];  // layer-1 accumulator
__device__ float g_deg[NN];                      // in-degree
__device__ __align__(16) float g_Z[NN * 32];     // [Z0(10),0*6 | Z1(10),0*6], 128B row
__device__ __align__(16) float g_R2[NN * 10];    // h@root2 + b2
__device__ __align__(16) float g_acc2[NN * 12];  // layer-2 accumulator (48B rows)

__device__ __forceinline__ void red_add_v4(float* a, float x, float y, float z, float w) {
    asm volatile("red.global.add.v4.f32 [%0], {%1, %2, %3, %4};"
                 :: "l"(a), "f"(x), "f"(y), "f"(z), "f"(w) : "memory");
}

// ---------------------------------------------------------------------------
// Node kernel 1: Y0 = x@W1[0], Y1 = x@W1[1], R1 = x@root1 + b1; zero acc1/deg
// ---------------------------------------------------------------------------
__global__ void node1_kernel(const float* __restrict__ x,
                             const float* __restrict__ W1,
                             const float* __restrict__ root1,
                             const float* __restrict__ b1)
{
    __shared__ float sW[1024];   // W1[k][i][o]
    __shared__ float sR[512];    // root1[i][o]
    __shared__ float sB[16];
    for (int t = threadIdx.x; t < 1024; t += blockDim.x) sW[t] = W1[t];
    for (int t = threadIdx.x; t < 512;  t += blockDim.x) sR[t] = root1[t];
    if (threadIdx.x < 16) sB[threadIdx.x] = b1[threadIdx.x];
    __syncthreads();

    int n = blockIdx.x * blockDim.x + threadIdx.x;
    if (n >= NN) return;

    float xv[32];
    const float4* xp = (const float4*)(x + (size_t)n * 32);
    #pragma unroll
    for (int i = 0; i < 8; i++) {
        float4 t = xp[i];
        xv[4*i+0] = t.x; xv[4*i+1] = t.y; xv[4*i+2] = t.z; xv[4*i+3] = t.w;
    }

    float* Yp = g_Y  + (size_t)n * 32;
    float* Rp = g_R1 + (size_t)n * 16;
    for (int o = 0; o < 16; o++) {
        float y0 = 0.f, y1 = 0.f, r = sB[o];
        #pragma unroll
        for (int i = 0; i < 32; i++) {
            y0 = fmaf(xv[i], sW[i * 16 + o], y0);
            y1 = fmaf(xv[i], sW[512 + i * 16 + o], y1);
            r  = fmaf(xv[i], sR[i * 16 + o], r);
        }
        Yp[o] = y0; Yp[16 + o] = y1; Rp[o] = r;
    }

    float4 zero = make_float4(0.f, 0.f, 0.f, 0.f);
    float4* ap = (float4*)(g_acc1 + (size_t)n * 16);
    ap[0] = zero; ap[1] = zero; ap[2] = zero; ap[3] = zero;
    g_deg[n] = 0.f;
}

// ---------------------------------------------------------------------------
// Edge kernel 1 (quad-cooperative): 4 lanes per edge, lane j handles floats
// [4j:4j+4). Quad lanes hit the SAME 128B line -> coalesced gather.
// ---------------------------------------------------------------------------
__global__ void edge1_kernel(const int* __restrict__ ei,
                             const float* __restrict__ attr)
{
    int gid = blockIdx.x * blockDim.x + threadIdx.x;
    int e = gid >> 2;
    if (e >= EE) return;
    int j = gid & 3;

    int s = ei[e];
    int d = ei[EE + e];
    if ((unsigned)s >= NN || (unsigned)d >= NN) return;  // defensive
    float v  = attr[e];
    float c0 = fmaxf(0.f, 1.f - fabsf(v));
    float c1 = fmaxf(0.f, 1.f - fabsf(v - 1.f));

    const float4* yp = (const float4*)(g_Y + (size_t)s * 32);
    float4 a = yp[j];        // Y0 chunk
    float4 b = yp[j + 4];    // Y1 chunk

    float* ap = g_acc1 + (size_t)d * 16 + 4 * j;
    red_add_v4(ap, c0*a.x + c1*b.x, c0*a.y + c1*b.y,
                   c0*a.z + c1*b.z, c0*a.w + c1*b.w);
    if (j == 0) atomicAdd(&g_deg[d], 1.0f);
}

// ---------------------------------------------------------------------------
// Node kernel 2: h = elu(acc1/deg + R1); Z (padded 32-float rows); zero acc2
// ---------------------------------------------------------------------------
__global__ void node2_kernel(const float* __restrict__ W2,
                             const float* __restrict__ root2,
                             const float* __restrict__ b2)
{
    __shared__ float sW[320];
    __shared__ float sR[160];
    __shared__ float sB[10];
    for (int t = threadIdx.x; t < 320; t += blockDim.x) sW[t] = W2[t];
    for (int t = threadIdx.x; t < 160; t += blockDim.x) sR[t] = root2[t];
    if (threadIdx.x < 10) sB[threadIdx.x] = b2[threadIdx.x];
    __syncthreads();

    int n = blockIdx.x * blockDim.x + threadIdx.x;
    if (n >= NN) return;

    float inv = 1.f / fmaxf(g_deg[n], 1.f);
    const float* ac = g_acc1 + (size_t)n * 16;
    const float* r1 = g_R1  + (size_t)n * 16;
    float h[16];
    #pragma unroll
    for (int o = 0; o < 16; o++) {
        float t = ac[o] * inv + r1[o];
        h[o] = (t > 0.f) ? t : expm1f(t);       // ELU alpha=1
    }

    float z[32];
    #pragma unroll
    for (int i = 0; i < 32; i++) z[i] = 0.f;
    float* r2 = g_R2 + (size_t)n * 10;
    for (int o = 0; o < 10; o++) {
        float z0 = 0.f, z1 = 0.f, r = sB[o];
        #pragma unroll
        for (int i = 0; i < 16; i++) {
            z0 = fmaf(h[i], sW[i * 10 + o], z0);
            z1 = fmaf(h[i], sW[160 + i * 10 + o], z1);
            r  = fmaf(h[i], sR[i * 10 + o], r);
        }
        z[o] = z0; z[16 + o] = z1; r2[o] = r;
    }
    float4* zp = (float4*)(g_Z + (size_t)n * 32);
    #pragma unroll
    for (int i = 0; i < 8; i++)
        zp[i] = make_float4(z[4*i], z[4*i+1], z[4*i+2], z[4*i+3]);

    float4 zero = make_float4(0.f, 0.f, 0.f, 0.f);
    float4* ap = (float4*)(g_acc2 + (size_t)n * 12);
    ap[0] = zero; ap[1] = zero; ap[2] = zero;
}

// ---------------------------------------------------------------------------
// Edge kernel 2 (quad-cooperative): lanes j=0..2 handle floats [4j:4j+4) of
// the 12-float (10 real + 2 zero-pad) message. Lane 3 idles.
// ---------------------------------------------------------------------------
__global__ void edge2_kernel(const int* __restrict__ ei,
                             const float* __restrict__ attr)
{
    int gid = blockIdx.x * blockDim.x + threadIdx.x;
    int e = gid >> 2;
    if (e >= EE) return;
    int j = gid & 3;
    if (j == 3) return;

    int s = ei[e];
    int d = ei[EE + e];
    if ((unsigned)s >= NN || (unsigned)d >= NN) return;
    float v  = attr[e];
    float c0 = fmaxf(0.f, 1.f - fabsf(v));
    float c1 = fmaxf(0.f, 1.f - fabsf(v - 1.f));

    const float4* zp = (const float4*)(g_Z + (size_t)s * 32);
    float4 a = zp[j];        // Z0 chunk (pad slots are zero)
    float4 b = zp[j + 4];    // Z1 chunk

    float* ap = g_acc2 + (size_t)d * 12 + 4 * j;
    red_add_v4(ap, c0*a.x + c1*b.x, c0*a.y + c1*b.y,
                   c0*a.z + c1*b.z, c0*a.w + c1*b.w);
}

// ---------------------------------------------------------------------------
// Output kernel: log_softmax(acc2/deg + R2)
// ---------------------------------------------------------------------------
__global__ void out_kernel(float* __restrict__ out)
{
    int n = blockIdx.x * blockDim.x + threadIdx.x;
    if (n >= NN) return;

    float inv = 1.f / fmaxf(g_deg[n], 1.f);
    const float* ac = g_acc2 + (size_t)n * 12;
    const float* r2 = g_R2  + (size_t)n * 10;
    float o[10];
    #pragma unroll
    for (int j = 0; j < 10; j++) o[j] = ac[j] * inv + r2[j];

    float mx = o[0];
    #pragma unroll
    for (int j = 1; j < 10; j++) mx = fmaxf(mx, o[j]);
    float sum = 0.f;
    #pragma unroll
    for (int j = 0; j < 10; j++) sum += expf(o[j] - mx);
    float lse = mx + logf(sum);

    float* op = out + (size_t)n * 10;
    #pragma unroll
    for (int j = 0; j < 10; j++) op[j] = o[j] - lse;
}

// ---------------------------------------------------------------------------
extern "C" void kernel_launch(void* const* d_in, const int* in_sizes, int n_in,
                              void* d_out, int out_size)
{
    (void)out_size;
    int ix = -1, iei = -1, iattr = -1, iW1 = -1, ir1 = -1, ib1 = -1,
        iW2 = -1, ir2 = -1, ib2 = -1;
    int big[2]; int nbig = 0;
    for (int i = 0; i < n_in; i++) {
        switch (in_sizes[i]) {
            case 3200000: if (nbig < 2) big[nbig++] = i; break;
            case 1600000: iattr = i; break;
            case 1024:    iW1 = i; break;
            case 512:     ir1 = i; break;
            case 16:      ib1 = i; break;
            case 320:     iW2 = i; break;
            case 160:     ir2 = i; break;
            case 10:      ib2 = i; break;
            default: break;
        }
    }
    if (nbig == 2) {
        bool insertion = (big[0] == 0 && big[1] == 1 && iattr == 2);
        if (insertion) { ix = big[0]; iei = big[1]; }
        else           { iei = big[0]; ix = big[1]; }
    }

    const float* x     = (const float*)d_in[ix];
    const int*   ei    = (const int*)d_in[iei];      // int32 edge_index
    const float* attr  = (const float*)d_in[iattr];
    const float* W1    = (const float*)d_in[iW1];
    const float* root1 = (const float*)d_in[ir1];
    const float* b1    = (const float*)d_in[ib1];
    const float* W2    = (const float*)d_in[iW2];
    const float* root2 = (const float*)d_in[ir2];
    const float* b2    = (const float*)d_in[ib2];
    float* out = (float*)d_out;

    node1_kernel<<<(NN + 255) / 256, 256>>>(x, W1, root1, b1);
    edge1_kernel<<<(EE * 4 + 255) / 256, 256>>>(ei, attr);
    node2_kernel<<<(NN + 255) / 256, 256>>>(W2, root2, b2);
    edge2_kernel<<<(EE * 4 + 255) / 256, 256>>>(ei, attr);
    out_kernel<<<(NN + 255) / 256, 256>>>(out);
}

// round 8
// speedup vs baseline: 1.8952x; 1.0600x over previous
#include <cuda_runtime.h>
#include <cuda_fp16.h>
#include <math.h>

#define NN 100000
#define EE 1600000

// ---- scratch (__device__ globals; no allocations allowed) ----
__device__ __align__(16) __half g_Yh[NN * 32];   // [Y0(16h)|Y1(16h)] per node, 64B row
__device__ __align__(16) float  g_R1[NN * 16];   // x@root1 + b1
__device__ __align__(16) float  g_acc1[NN * 16]; // layer-1 accumulator
__device__ float g_deg[NN];                      // in-degree
__device__ __align__(16) __half g_Zh[NN * 32];   // [Z0(10h)+pad6 | Z1(10h)+pad6], 64B row
__device__ __align__(16) float  g_R2[NN * 10];   // h@root2 + b2
__device__ __align__(16) float  g_acc2[NN * 12]; // layer-2 accumulator (48B rows)

__device__ __forceinline__ void red_add_v4(float* a, float x, float y, float z, float w) {
    asm volatile("red.global.add.v4.f32 [%0], {%1, %2, %3, %4};"
                 :: "l"(a), "f"(x), "f"(y), "f"(z), "f"(w) : "memory");
}
__device__ __forceinline__ unsigned packh2(float a, float b) {
    __half2 h = __floats2half2_rn(a, b);
    return *reinterpret_cast<unsigned*>(&h);
}
__device__ __forceinline__ float2 unph2(unsigned u) {
    __half2 h = *reinterpret_cast<__half2*>(&u);
    return __half22float2(h);
}

// ---------------------------------------------------------------------------
// Node kernel 1: Yh = fp16{x@W1[0], x@W1[1]}, R1 = x@root1 + b1; zero acc/deg
// ---------------------------------------------------------------------------
__global__ void node1_kernel(const float* __restrict__ x,
                             const float* __restrict__ W1,
                             const float* __restrict__ root1,
                             const float* __restrict__ b1)
{
    __shared__ float sW[1024];   // W1[k][i][o]
    __shared__ float sR[512];    // root1[i][o]
    __shared__ float sB[16];
    for (int t = threadIdx.x; t < 1024; t += blockDim.x) sW[t] = W1[t];
    for (int t = threadIdx.x; t < 512;  t += blockDim.x) sR[t] = root1[t];
    if (threadIdx.x < 16) sB[threadIdx.x] = b1[threadIdx.x];
    __syncthreads();

    int n = blockIdx.x * blockDim.x + threadIdx.x;
    if (n >= NN) return;

    float xv[32];
    const float4* xp = (const float4*)(x + (size_t)n * 32);
    #pragma unroll
    for (int i = 0; i < 8; i++) {
        float4 t = xp[i];
        xv[4*i+0] = t.x; xv[4*i+1] = t.y; xv[4*i+2] = t.z; xv[4*i+3] = t.w;
    }

    float y0v[16], y1v[16];
    float* Rp = g_R1 + (size_t)n * 16;
    for (int o = 0; o < 16; o++) {
        float y0 = 0.f, y1 = 0.f, r = sB[o];
        #pragma unroll
        for (int i = 0; i < 32; i++) {
            y0 = fmaf(xv[i], sW[i * 16 + o], y0);
            y1 = fmaf(xv[i], sW[512 + i * 16 + o], y1);
            r  = fmaf(xv[i], sR[i * 16 + o], r);
        }
        y0v[o] = y0; y1v[o] = y1; Rp[o] = r;
    }

    uint4* yo = (uint4*)(g_Yh + (size_t)n * 32);
    #pragma unroll
    for (int c = 0; c < 2; c++)   // Y0 halves
        yo[c] = make_uint4(packh2(y0v[8*c+0], y0v[8*c+1]), packh2(y0v[8*c+2], y0v[8*c+3]),
                           packh2(y0v[8*c+4], y0v[8*c+5]), packh2(y0v[8*c+6], y0v[8*c+7]));
    #pragma unroll
    for (int c = 0; c < 2; c++)   // Y1 halves
        yo[2+c] = make_uint4(packh2(y1v[8*c+0], y1v[8*c+1]), packh2(y1v[8*c+2], y1v[8*c+3]),
                             packh2(y1v[8*c+4], y1v[8*c+5]), packh2(y1v[8*c+6], y1v[8*c+7]));

    float4 zero = make_float4(0.f, 0.f, 0.f, 0.f);
    float4* ap = (float4*)(g_acc1 + (size_t)n * 16);
    ap[0] = zero; ap[1] = zero; ap[2] = zero; ap[3] = zero;
    g_deg[n] = 0.f;
}

// ---------------------------------------------------------------------------
// Edge kernel 1 (lane-pair): 2 lanes per edge, lane j handles features
// [8j:8j+8). Each lane: 2x LDG.128 (fp16), lerp fp32, 2x red.v4.f32.
// ---------------------------------------------------------------------------
__global__ void edge1_kernel(const int* __restrict__ ei,
                             const float* __restrict__ attr)
{
    int gid = blockIdx.x * blockDim.x + threadIdx.x;
    int e = gid >> 1;
    if (e >= EE) return;
    int j = gid & 1;

    int s = ei[e];
    int d = ei[EE + e];
    if ((unsigned)s >= NN || (unsigned)d >= NN) return;  // defensive
    float v  = attr[e];
    float c0 = fmaxf(0.f, 1.f - fabsf(v));
    float c1 = fmaxf(0.f, 1.f - fabsf(v - 1.f));

    const uint4* yp = (const uint4*)(g_Yh + (size_t)s * 32);
    uint4 A = yp[j];       // Y0 halves [8j..8j+8)
    uint4 B = yp[j + 2];   // Y1 halves [8j..8j+8)

    float2 a0 = unph2(A.x), a1 = unph2(A.y), a2 = unph2(A.z), a3 = unph2(A.w);
    float2 b0 = unph2(B.x), b1 = unph2(B.y), b2 = unph2(B.z), b3 = unph2(B.w);

    float* ap = g_acc1 + (size_t)d * 16 + 8 * j;
    red_add_v4(ap,     c0*a0.x + c1*b0.x, c0*a0.y + c1*b0.y,
                       c0*a1.x + c1*b1.x, c0*a1.y + c1*b1.y);
    red_add_v4(ap + 4, c0*a2.x + c1*b2.x, c0*a2.y + c1*b2.y,
                       c0*a3.x + c1*b3.x, c0*a3.y + c1*b3.y);
    if (j == 0) atomicAdd(&g_deg[d], 1.0f);
}

// ---------------------------------------------------------------------------
// Node kernel 2: h = elu(acc1/deg + R1); Zh fp16 padded rows; zero acc2
// ---------------------------------------------------------------------------
__global__ void node2_kernel(const float* __restrict__ W2,
                             const float* __restrict__ root2,
                             const float* __restrict__ b2)
{
    __shared__ float sW[320];
    __shared__ float sR[160];
    __shared__ float sB[10];
    for (int t = threadIdx.x; t < 320; t += blockDim.x) sW[t] = W2[t];
    for (int t = threadIdx.x; t < 160; t += blockDim.x) sR[t] = root2[t];
    if (threadIdx.x < 10) sB[threadIdx.x] = b2[threadIdx.x];
    __syncthreads();

    int n = blockIdx.x * blockDim.x + threadIdx.x;
    if (n >= NN) return;

    float inv = 1.f / fmaxf(g_deg[n], 1.f);
    const float* ac = g_acc1 + (size_t)n * 16;
    const float* r1 = g_R1  + (size_t)n * 16;
    float h[16];
    #pragma unroll
    for (int o = 0; o < 16; o++) {
        float t = ac[o] * inv + r1[o];
        h[o] = (t > 0.f) ? t : expm1f(t);       // ELU alpha=1
    }

    float z0v[16], z1v[16];
    #pragma unroll
    for (int i = 0; i < 16; i++) { z0v[i] = 0.f; z1v[i] = 0.f; }
    float* r2 = g_R2 + (size_t)n * 10;
    for (int o = 0; o < 10; o++) {
        float z0 = 0.f, z1 = 0.f, r = sB[o];
        #pragma unroll
        for (int i = 0; i < 16; i++) {
            z0 = fmaf(h[i], sW[i * 10 + o], z0);
            z1 = fmaf(h[i], sW[160 + i * 10 + o], z1);
            r  = fmaf(h[i], sR[i * 10 + o], r);
        }
        z0v[o] = z0; z1v[o] = z1; r2[o] = r;
    }

    uint4* zo = (uint4*)(g_Zh + (size_t)n * 32);
    #pragma unroll
    for (int c = 0; c < 2; c++)
        zo[c] = make_uint4(packh2(z0v[8*c+0], z0v[8*c+1]), packh2(z0v[8*c+2], z0v[8*c+3]),
                           packh2(z0v[8*c+4], z0v[8*c+5]), packh2(z0v[8*c+6], z0v[8*c+7]));
    #pragma unroll
    for (int c = 0; c < 2; c++)
        zo[2+c] = make_uint4(packh2(z1v[8*c+0], z1v[8*c+1]), packh2(z1v[8*c+2], z1v[8*c+3]),
                             packh2(z1v[8*c+4], z1v[8*c+5]), packh2(z1v[8*c+6], z1v[8*c+7]));

    float4 zero = make_float4(0.f, 0.f, 0.f, 0.f);
    float4* ap = (float4*)(g_acc2 + (size_t)n * 12);
    ap[0] = zero; ap[1] = zero; ap[2] = zero;
}

// ---------------------------------------------------------------------------
// Edge kernel 2 (lane-pair): lane 0 -> features [0:8) (2 reds),
// lane 1 -> features [8:10) + 2 pads (1 red).
// ---------------------------------------------------------------------------
__global__ void edge2_kernel(const int* __restrict__ ei,
                             const float* __restrict__ attr)
{
    int gid = blockIdx.x * blockDim.x + threadIdx.x;
    int e = gid >> 1;
    if (e >= EE) return;
    int j = gid & 1;

    int s = ei[e];
    int d = ei[EE + e];
    if ((unsigned)s >= NN || (unsigned)d >= NN) return;
    float v  = attr[e];
    float c0 = fmaxf(0.f, 1.f - fabsf(v));
    float c1 = fmaxf(0.f, 1.f - fabsf(v - 1.f));

    const uint4* zp = (const uint4*)(g_Zh + (size_t)s * 32);
    uint4 A = zp[j];       // Z0 halves [8j..8j+8)  (pads zero)
    uint4 B = zp[j + 2];   // Z1 halves [8j..8j+8)

    float2 a0 = unph2(A.x), a1 = unph2(A.y);
    float2 b0 = unph2(B.x), b1 = unph2(B.y);

    float* ap = g_acc2 + (size_t)d * 12 + 8 * j;
    red_add_v4(ap, c0*a0.x + c1*b0.x, c0*a0.y + c1*b0.y,
                   c0*a1.x + c1*b1.x, c0*a1.y + c1*b1.y);
    if (j == 0) {
        float2 a2 = unph2(A.z), a3 = unph2(A.w);
        float2 b2 = unph2(B.z), b3 = unph2(B.w);
        red_add_v4(ap + 4, c0*a2.x + c1*b2.x, c0*a2.y + c1*b2.y,
                           c0*a3.x + c1*b3.x, c0*a3.y + c1*b3.y);
    }
}

// ---------------------------------------------------------------------------
// Output kernel: log_softmax(acc2/deg + R2)
// ---------------------------------------------------------------------------
__global__ void out_kernel(float* __restrict__ out)
{
    int n = blockIdx.x * blockDim.x + threadIdx.x;
    if (n >= NN) return;

    float inv = 1.f / fmaxf(g_deg[n], 1.f);
    const float* ac = g_acc2 + (size_t)n * 12;
    const float* r2 = g_R2  + (size_t)n * 10;
    float o[10];
    #pragma unroll
    for (int j = 0; j < 10; j++) o[j] = ac[j] * inv + r2[j];

    float mx = o[0];
    #pragma unroll
    for (int j = 1; j < 10; j++) mx = fmaxf(mx, o[j]);
    float sum = 0.f;
    #pragma unroll
    for (int j = 0; j < 10; j++) sum += expf(o[j] - mx);
    float lse = mx + logf(sum);

    float* op = out + (size_t)n * 10;
    #pragma unroll
    for (int j = 0; j < 10; j++) op[j] = o[j] - lse;
}

// ---------------------------------------------------------------------------
extern "C" void kernel_launch(void* const* d_in, const int* in_sizes, int n_in,
                              void* d_out, int out_size)
{
    (void)out_size;
    int ix = -1, iei = -1, iattr = -1, iW1 = -1, ir1 = -1, ib1 = -1,
        iW2 = -1, ir2 = -1, ib2 = -1;
    int big[2]; int nbig = 0;
    for (int i = 0; i < n_in; i++) {
        switch (in_sizes[i]) {
            case 3200000: if (nbig < 2) big[nbig++] = i; break;
            case 1600000: iattr = i; break;
            case 1024:    iW1 = i; break;
            case 512:     ir1 = i; break;
            case 16:      ib1 = i; break;
            case 320:     iW2 = i; break;
            case 160:     ir2 = i; break;
            case 10:      ib2 = i; break;
            default: break;
        }
    }
    if (nbig == 2) {
        bool insertion = (big[0] == 0 && big[1] == 1 && iattr == 2);
        if (insertion) { ix = big[0]; iei = big[1]; }
        else           { iei = big[0]; ix = big[1]; }
    }

    const float* x     = (const float*)d_in[ix];
    const int*   ei    = (const int*)d_in[iei];      // int32 edge_index
    const float* attr  = (const float*)d_in[iattr];
    const float* W1    = (const float*)d_in[iW1];
    const float* root1 = (const float*)d_in[ir1];
    const float* b1    = (const float*)d_in[ib1];
    const float* W2    = (const float*)d_in[iW2];
    const float* root2 = (const float*)d_in[ir2];
    const float* b2    = (const float*)d_in[ib2];
    float* out = (float*)d_out;

    node1_kernel<<<(NN + 255) / 256, 256>>>(x, W1, root1, b1);
    edge1_kernel<<<(EE * 2 + 255) / 256, 256>>>(ei, attr);
    node2_kernel<<<(NN + 255) / 256, 256>>>(W2, root2, b2);
    edge2_kernel<<<(EE * 2 + 255) / 256, 256>>>(ei, attr);
    out_kernel<<<(NN + 255) / 256, 256>>>(out);
}

// round 9
// speedup vs baseline: 2.2711x; 1.1983x over previous
#include <cuda_runtime.h>
#include <cuda_fp16.h>
#include <math.h>

#define NN 100000
#define EE 1600000

// ---- scratch (__device__ globals; no allocations allowed) ----
__device__ __align__(16) __half g_Yh[NN * 32];    // [Y0(16h)|Y1(16h)] per node, 64B row
__device__ __align__(16) float  g_R1[NN * 16];    // x@root1 + b1
__device__ __align__(16) __half g_acc1h[NN * 16]; // layer-1 fp16 accumulator, 32B row
__device__ float g_deg[NN];                       // in-degree
__device__ __align__(16) __half g_Zh[NN * 32];    // [Z0(10h)+pad6 | Z1(10h)+pad6], 64B row
__device__ __align__(16) float  g_R2[NN * 10];    // h@root2 + b2
__device__ __align__(16) __half g_acc2h[NN * 16]; // layer-2 fp16 accumulator, 32B row

__device__ __forceinline__ void red_add_v4h2(__half* a, unsigned p0, unsigned p1,
                                             unsigned p2, unsigned p3) {
    asm volatile("red.global.add.noftz.v4.f16x2 [%0], {%1, %2, %3, %4};"
                 :: "l"(a), "r"(p0), "r"(p1), "r"(p2), "r"(p3) : "memory");
}
__device__ __forceinline__ unsigned packh2(float a, float b) {
    __half2 h = __floats2half2_rn(a, b);
    return *reinterpret_cast<unsigned*>(&h);
}
__device__ __forceinline__ float2 unph2(unsigned u) {
    __half2 h = *reinterpret_cast<__half2*>(&u);
    return __half22float2(h);
}

// ---------------------------------------------------------------------------
// Node kernel 1: Yh = fp16{x@W1[0], x@W1[1]}, R1 = x@root1 + b1; zero acc/deg
// ---------------------------------------------------------------------------
__global__ void node1_kernel(const float* __restrict__ x,
                             const float* __restrict__ W1,
                             const float* __restrict__ root1,
                             const float* __restrict__ b1)
{
    __shared__ float sW[1024];   // W1[k][i][o]
    __shared__ float sR[512];    // root1[i][o]
    __shared__ float sB[16];
    for (int t = threadIdx.x; t < 1024; t += blockDim.x) sW[t] = W1[t];
    for (int t = threadIdx.x; t < 512;  t += blockDim.x) sR[t] = root1[t];
    if (threadIdx.x < 16) sB[threadIdx.x] = b1[threadIdx.x];
    __syncthreads();

    int n = blockIdx.x * blockDim.x + threadIdx.x;
    if (n >= NN) return;

    float xv[32];
    const float4* xp = (const float4*)(x + (size_t)n * 32);
    #pragma unroll
    for (int i = 0; i < 8; i++) {
        float4 t = xp[i];
        xv[4*i+0] = t.x; xv[4*i+1] = t.y; xv[4*i+2] = t.z; xv[4*i+3] = t.w;
    }

    float y0v[16], y1v[16];
    float* Rp = g_R1 + (size_t)n * 16;
    for (int o = 0; o < 16; o++) {
        float y0 = 0.f, y1 = 0.f, r = sB[o];
        #pragma unroll
        for (int i = 0; i < 32; i++) {
            y0 = fmaf(xv[i], sW[i * 16 + o], y0);
            y1 = fmaf(xv[i], sW[512 + i * 16 + o], y1);
            r  = fmaf(xv[i], sR[i * 16 + o], r);
        }
        y0v[o] = y0; y1v[o] = y1; Rp[o] = r;
    }

    uint4* yo = (uint4*)(g_Yh + (size_t)n * 32);
    #pragma unroll
    for (int c = 0; c < 2; c++)
        yo[c] = make_uint4(packh2(y0v[8*c+0], y0v[8*c+1]), packh2(y0v[8*c+2], y0v[8*c+3]),
                           packh2(y0v[8*c+4], y0v[8*c+5]), packh2(y0v[8*c+6], y0v[8*c+7]));
    #pragma unroll
    for (int c = 0; c < 2; c++)
        yo[2+c] = make_uint4(packh2(y1v[8*c+0], y1v[8*c+1]), packh2(y1v[8*c+2], y1v[8*c+3]),
                             packh2(y1v[8*c+4], y1v[8*c+5]), packh2(y1v[8*c+6], y1v[8*c+7]));

    uint4 z4 = make_uint4(0u, 0u, 0u, 0u);
    uint4* ap = (uint4*)(g_acc1h + (size_t)n * 16);
    ap[0] = z4; ap[1] = z4;
    g_deg[n] = 0.f;
}

// ---------------------------------------------------------------------------
// Edge kernel 1 (lane-pair): lane j handles features [8j:8j+8).
// Gather 16B fp16 chunks, lerp fp32, ONE red.v4.f16x2 per lane.
// ---------------------------------------------------------------------------
__global__ void edge1_kernel(const int* __restrict__ ei,
                             const float* __restrict__ attr)
{
    int gid = blockIdx.x * blockDim.x + threadIdx.x;
    int e = gid >> 1;
    if (e >= EE) return;
    int j = gid & 1;

    int s = ei[e];
    int d = ei[EE + e];
    if ((unsigned)s >= NN || (unsigned)d >= NN) return;  // defensive
    float v  = attr[e];
    float c0 = fmaxf(0.f, 1.f - fabsf(v));
    float c1 = fmaxf(0.f, 1.f - fabsf(v - 1.f));

    const uint4* yp = (const uint4*)(g_Yh + (size_t)s * 32);
    uint4 A = yp[j];       // Y0 halves [8j..8j+8)
    uint4 B = yp[j + 2];   // Y1 halves [8j..8j+8)

    float2 a0 = unph2(A.x), a1 = unph2(A.y), a2 = unph2(A.z), a3 = unph2(A.w);
    float2 b0 = unph2(B.x), b1 = unph2(B.y), b2 = unph2(B.z), b3 = unph2(B.w);

    unsigned p0 = packh2(c0*a0.x + c1*b0.x, c0*a0.y + c1*b0.y);
    unsigned p1 = packh2(c0*a1.x + c1*b1.x, c0*a1.y + c1*b1.y);
    unsigned p2 = packh2(c0*a2.x + c1*b2.x, c0*a2.y + c1*b2.y);
    unsigned p3 = packh2(c0*a3.x + c1*b3.x, c0*a3.y + c1*b3.y);

    red_add_v4h2(g_acc1h + (size_t)d * 16 + 8 * j, p0, p1, p2, p3);
    if (j == 0) atomicAdd(&g_deg[d], 1.0f);
}

// ---------------------------------------------------------------------------
// Node kernel 2: h = elu(acc1h/deg + R1); Zh fp16 padded rows; zero acc2h
// ---------------------------------------------------------------------------
__global__ void node2_kernel(const float* __restrict__ W2,
                             const float* __restrict__ root2,
                             const float* __restrict__ b2)
{
    __shared__ float sW[320];
    __shared__ float sR[160];
    __shared__ float sB[10];
    for (int t = threadIdx.x; t < 320; t += blockDim.x) sW[t] = W2[t];
    for (int t = threadIdx.x; t < 160; t += blockDim.x) sR[t] = root2[t];
    if (threadIdx.x < 10) sB[threadIdx.x] = b2[threadIdx.x];
    __syncthreads();

    int n = blockIdx.x * blockDim.x + threadIdx.x;
    if (n >= NN) return;

    float inv = 1.f / fmaxf(g_deg[n], 1.f);
    const uint4* ah = (const uint4*)(g_acc1h + (size_t)n * 16);
    uint4 u0 = ah[0], u1 = ah[1];
    float ac[16];
    {
        float2 t;
        t = unph2(u0.x); ac[0]=t.x; ac[1]=t.y;
        t = unph2(u0.y); ac[2]=t.x; ac[3]=t.y;
        t = unph2(u0.z); ac[4]=t.x; ac[5]=t.y;
        t = unph2(u0.w); ac[6]=t.x; ac[7]=t.y;
        t = unph2(u1.x); ac[8]=t.x; ac[9]=t.y;
        t = unph2(u1.y); ac[10]=t.x; ac[11]=t.y;
        t = unph2(u1.z); ac[12]=t.x; ac[13]=t.y;
        t = unph2(u1.w); ac[14]=t.x; ac[15]=t.y;
    }
    const float* r1 = g_R1 + (size_t)n * 16;
    float h[16];
    #pragma unroll
    for (int o = 0; o < 16; o++) {
        float t = ac[o] * inv + r1[o];
        h[o] = (t > 0.f) ? t : expm1f(t);       // ELU alpha=1
    }

    float z0v[16], z1v[16];
    #pragma unroll
    for (int i = 0; i < 16; i++) { z0v[i] = 0.f; z1v[i] = 0.f; }
    float* r2 = g_R2 + (size_t)n * 10;
    for (int o = 0; o < 10; o++) {
        float z0 = 0.f, z1 = 0.f, r = sB[o];
        #pragma unroll
        for (int i = 0; i < 16; i++) {
            z0 = fmaf(h[i], sW[i * 10 + o], z0);
            z1 = fmaf(h[i], sW[160 + i * 10 + o], z1);
            r  = fmaf(h[i], sR[i * 10 + o], r);
        }
        z0v[o] = z0; z1v[o] = z1; r2[o] = r;
    }

    uint4* zo = (uint4*)(g_Zh + (size_t)n * 32);
    #pragma unroll
    for (int c = 0; c < 2; c++)
        zo[c] = make_uint4(packh2(z0v[8*c+0], z0v[8*c+1]), packh2(z0v[8*c+2], z0v[8*c+3]),
                           packh2(z0v[8*c+4], z0v[8*c+5]), packh2(z0v[8*c+6], z0v[8*c+7]));
    #pragma unroll
    for (int c = 0; c < 2; c++)
        zo[2+c] = make_uint4(packh2(z1v[8*c+0], z1v[8*c+1]), packh2(z1v[8*c+2], z1v[8*c+3]),
                             packh2(z1v[8*c+4], z1v[8*c+5]), packh2(z1v[8*c+6], z1v[8*c+7]));

    uint4 z4 = make_uint4(0u, 0u, 0u, 0u);
    uint4* ap = (uint4*)(g_acc2h + (size_t)n * 16);
    ap[0] = z4; ap[1] = z4;
}

// ---------------------------------------------------------------------------
// Edge kernel 2 (lane-pair): lane j reds halves [8j:8j+8) (pads are zero).
// ---------------------------------------------------------------------------
__global__ void edge2_kernel(const int* __restrict__ ei,
                             const float* __restrict__ attr)
{
    int gid = blockIdx.x * blockDim.x + threadIdx.x;
    int e = gid >> 1;
    if (e >= EE) return;
    int j = gid & 1;

    int s = ei[e];
    int d = ei[EE + e];
    if ((unsigned)s >= NN || (unsigned)d >= NN) return;
    float v  = attr[e];
    float c0 = fmaxf(0.f, 1.f - fabsf(v));
    float c1 = fmaxf(0.f, 1.f - fabsf(v - 1.f));

    const uint4* zp = (const uint4*)(g_Zh + (size_t)s * 32);
    uint4 A = zp[j];       // Z0 halves [8j..8j+8)  (pads zero)
    uint4 B = zp[j + 2];   // Z1 halves [8j..8j+8)

    float2 a0 = unph2(A.x), a1 = unph2(A.y), a2 = unph2(A.z), a3 = unph2(A.w);
    float2 b0 = unph2(B.x), b1 = unph2(B.y), b2 = unph2(B.z), b3 = unph2(B.w);

    unsigned p0 = packh2(c0*a0.x + c1*b0.x, c0*a0.y + c1*b0.y);
    unsigned p1 = packh2(c0*a1.x + c1*b1.x, c0*a1.y + c1*b1.y);
    unsigned p2 = packh2(c0*a2.x + c1*b2.x, c0*a2.y + c1*b2.y);
    unsigned p3 = packh2(c0*a3.x + c1*b3.x, c0*a3.y + c1*b3.y);

    red_add_v4h2(g_acc2h + (size_t)d * 16 + 8 * j, p0, p1, p2, p3);
}

// ---------------------------------------------------------------------------
// Output kernel: log_softmax(acc2h/deg + R2)
// ---------------------------------------------------------------------------
__global__ void out_kernel(float* __restrict__ out)
{
    int n = blockIdx.x * blockDim.x + threadIdx.x;
    if (n >= NN) return;

    float inv = 1.f / fmaxf(g_deg[n], 1.f);
    const uint4* ah = (const uint4*)(g_acc2h + (size_t)n * 16);
    uint4 u0 = ah[0], u1 = ah[1];
    float ac[10];
    {
        float2 t;
        t = unph2(u0.x); ac[0]=t.x; ac[1]=t.y;
        t = unph2(u0.y); ac[2]=t.x; ac[3]=t.y;
        t = unph2(u0.z); ac[4]=t.x; ac[5]=t.y;
        t = unph2(u0.w); ac[6]=t.x; ac[7]=t.y;
        t = unph2(u1.x); ac[8]=t.x; ac[9]=t.y;
    }
    const float* r2 = g_R2 + (size_t)n * 10;
    float o[10];
    #pragma unroll
    for (int j = 0; j < 10; j++) o[j] = ac[j] * inv + r2[j];

    float mx = o[0];
    #pragma unroll
    for (int j = 1; j < 10; j++) mx = fmaxf(mx, o[j]);
    float sum = 0.f;
    #pragma unroll
    for (int j = 0; j < 10; j++) sum += expf(o[j] - mx);
    float lse = mx + logf(sum);

    float* op = out + (size_t)n * 10;
    #pragma unroll
    for (int j = 0; j < 10; j++) op[j] = o[j] - lse;
}

// ---------------------------------------------------------------------------
extern "C" void kernel_launch(void* const* d_in, const int* in_sizes, int n_in,
                              void* d_out, int out_size)
{
    (void)out_size;
    int ix = -1, iei = -1, iattr = -1, iW1 = -1, ir1 = -1, ib1 = -1,
        iW2 = -1, ir2 = -1, ib2 = -1;
    int big[2]; int nbig = 0;
    for (int i = 0; i < n_in; i++) {
        switch (in_sizes[i]) {
            case 3200000: if (nbig < 2) big[nbig++] = i; break;
            case 1600000: iattr = i; break;
            case 1024:    iW1 = i; break;
            case 512:     ir1 = i; break;
            case 16:      ib1 = i; break;
            case 320:     iW2 = i; break;
            case 160:     ir2 = i; break;
            case 10:      ib2 = i; break;
            default: break;
        }
    }
    if (nbig == 2) {
        bool insertion = (big[0] == 0 && big[1] == 1 && iattr == 2);
        if (insertion) { ix = big[0]; iei = big[1]; }
        else           { iei = big[0]; ix = big[1]; }
    }

    const float* x     = (const float*)d_in[ix];
    const int*   ei    = (const int*)d_in[iei];      // int32 edge_index
    const float* attr  = (const float*)d_in[iattr];
    const float* W1    = (const float*)d_in[iW1];
    const float* root1 = (const float*)d_in[ir1];
    const float* b1    = (const float*)d_in[ib1];
    const float* W2    = (const float*)d_in[iW2];
    const float* root2 = (const float*)d_in[ir2];
    const float* b2    = (const float*)d_in[ib2];
    float* out = (float*)d_out;

    node1_kernel<<<(NN + 255) / 256, 256>>>(x, W1, root1, b1);
    edge1_kernel<<<(EE * 2 + 255) / 256, 256>>>(ei, attr);
    node2_kernel<<<(NN + 255) / 256, 256>>>(W2, root2, b2);
    edge2_kernel<<<(EE * 2 + 255) / 256, 256>>>(ei, attr);
    out_kernel<<<(NN + 255) / 256, 256>>>(out);
}